// round 16
// baseline (speedup 1.0000x reference)
#include <cuda_runtime.h>
#include <cuda_fp16.h>
#include <cstdint>

// ---------------- Problem constants ----------------
#define U      1024
#define BATCH  4
#define NCHAN  2
#define TLEN   1024
#define HEADS  8
#define DK     128
#define MROWS  (BATCH * NCHAN * TLEN)          // 8192
#define MS     ((size_t)MROWS * U)             // 8M elements
#define ATTN_E ((size_t)BATCH * HEADS * TLEN * TLEN)  // 32M elements

// Weight pre-scale (exact power of two) keeps fp16 weights in normal range;
// epilogues compensate with alpha = 1/WSCALE.
#define WSCALE     32.0f
#define INV_WSCALE 0.03125f

// ---------------- Scratch (device globals; allocation-free) ----------------
__device__ __half g_xh[MS];                      // x: fp16
__device__ __half g_Wqh[U*U], g_Wkh[U*U], g_Wvh[U*U], g_Woh[U*U];
__device__ __half g_Qh[MS];                      // scores A
__device__ __half g_Kh[MS];                      // scores B
__device__ __half g_Vh[MS];                      // V untransposed, fp16
__device__ __half g_Vth[MS];                     // V transposed, fp16
__device__ __half g_sco[ATTN_E];                 // raw scores, fp16
__device__ __half g_atth[ATTN_E];                // softmaxed att, fp16 (attv A)
__device__ __half g_aoh[MS];                     // attention out (out-proj A)

// ---------------- Helpers ----------------
__device__ __forceinline__ uint32_t smem_u32(const void* p) {
    uint32_t a;
    asm("{ .reg .u64 t; cvta.to.shared.u64 t, %1; cvt.u32.u64 %0, t; }" : "=r"(a) : "l"(p));
    return a;
}
__device__ __forceinline__ void cp16(uint32_t dst, const void* src) {
    asm volatile("cp.async.cg.shared.global [%0], [%1], 16;" :: "r"(dst), "l"(src));
}
#define CP_COMMIT asm volatile("cp.async.commit_group;" ::: "memory")
#define CP_WAIT(n) asm volatile("cp.async.wait_group %0;" :: "n"(n) : "memory")

__device__ __forceinline__ void ldsm4(uint32_t (&r)[4], uint32_t addr) {
    asm volatile("ldmatrix.sync.aligned.m8n8.x4.shared.b16 {%0,%1,%2,%3}, [%4];"
        : "=r"(r[0]), "=r"(r[1]), "=r"(r[2]), "=r"(r[3]) : "r"(addr));
}
__device__ __forceinline__ void mma16816(float (&c)[4], const uint32_t (&a)[4],
                                         uint32_t b0, uint32_t b1) {
    asm volatile(
        "mma.sync.aligned.m16n8k16.row.col.f32.f16.f16.f32 "
        "{%0,%1,%2,%3}, {%4,%5,%6,%7}, {%8,%9}, {%0,%1,%2,%3};"
        : "+f"(c[0]), "+f"(c[1]), "+f"(c[2]), "+f"(c[3])
        : "r"(a[0]), "r"(a[1]), "r"(a[2]), "r"(a[3]), "r"(b0), "r"(b1));
}

// ---------------- fp16 GEMM core (mma.sync) ----------------
// C[128,128] = alpha*(A@B^T) + bias.  A, B fp16, K-major.
// 256 threads. Tile smem: 128 rows x 32 fp16, row stride 80B -> 10240B/tile.
#define SM_AH    0
#define SM_BH    10240
#define SMEM_STAGE 20480
#define SMEM_BYTES (2 * SMEM_STAGE)

__device__ __forceinline__ void stage_tile(uint32_t sdst, const __half* __restrict__ g,
                                           int ld, int tid) {
#pragma unroll
    for (int p = 0; p < 2; ++p) {
        int idx = p * 256 + tid;        // 512 chunks of 16B
        int row = idx >> 2, c = idx & 3;
        cp16(sdst + row * 80 + c * 16, g + (size_t)row * ld + c * 8);
    }
}

// MODE 0: fp32 out (Cf). MODE 2: fp16 out (Ch).
template <int NST, int MODE, bool HAS_BIAS>
__device__ __forceinline__ void gemm_core(
    const __half* __restrict__ Ah, int lda,
    const __half* __restrict__ Bh, int ldb,
    float alpha, const float* __restrict__ bias,
    float* Cf, __half* Ch, int ldc)
{
    extern __shared__ char smem[];
    const uint32_t sb = smem_u32(smem);
    const int tid = threadIdx.x;
    const int l   = tid & 31;
    const int wid = tid >> 5;
    const int wm  = wid >> 1;      // 0..3 -> M
    const int wn  = wid & 1;       // 0..1 -> N

    const uint32_t lrow = (uint32_t)(l & 15) * 80 + (uint32_t)(l >> 4) * 16;
    const uint32_t aoff = (uint32_t)(wm * 32) * 80 + lrow;
    const uint32_t boff = (uint32_t)(wn * 64) * 80 + lrow;

    float acc[2][8][4];
#pragma unroll
    for (int i = 0; i < 2; ++i)
#pragma unroll
        for (int j = 0; j < 8; ++j)
#pragma unroll
            for (int q = 0; q < 4; ++q) acc[i][j][q] = 0.0f;

    // prologue: stage 0
    stage_tile(sb + SM_AH, Ah, lda, tid);
    stage_tile(sb + SM_BH, Bh, ldb, tid);
    CP_COMMIT;

    for (int st = 0; st < NST; ++st) {
        CP_WAIT(0);
        __syncthreads();       // single barrier per stage (buffer reuse is
                               // transitively protected across 2 stages)

        if (st + 1 < NST) {    // overlap next-stage copies with this stage's MMAs
            const uint32_t so2 = (uint32_t)((st + 1) & 1) * SMEM_STAGE;
            const int k0 = (st + 1) << 5;
            stage_tile(sb + so2 + SM_AH, Ah + k0, lda, tid);
            stage_tile(sb + so2 + SM_BH, Bh + k0, ldb, tid);
            CP_COMMIT;
        }

        const uint32_t so = (uint32_t)(st & 1) * SMEM_STAGE;
#pragma unroll
        for (int k16 = 0; k16 < 2; ++k16) {
            const uint32_t kb = (uint32_t)k16 * 32;
            uint32_t ah[2][4];
#pragma unroll
            for (int i = 0; i < 2; ++i)
                ldsm4(ah[i], sb + so + SM_AH + aoff + i * (16 * 80) + kb);
#pragma unroll
            for (int j2 = 0; j2 < 4; ++j2) {
                uint32_t bh[4];
                ldsm4(bh, sb + so + SM_BH + boff + j2 * (16 * 80) + kb);
#pragma unroll
                for (int jj = 0; jj < 2; ++jj) {
#pragma unroll
                    for (int i = 0; i < 2; ++i) {
                        const int j = j2 * 2 + jj;
                        mma16816(acc[i][j], ah[i], bh[jj], bh[jj + 2]);
                    }
                }
            }
        }
    }

    // ---- Epilogue ----
    const int rbase = wm * 32 + (l >> 2);
    const int cbase = wn * 64 + 2 * (l & 3);
#pragma unroll
    for (int i = 0; i < 2; ++i) {
#pragma unroll
        for (int j = 0; j < 8; ++j) {
            const int row = rbase + i * 16;
            const int col = cbase + j * 8;
            float b0 = 0.0f, b1 = 0.0f;
            if (HAS_BIAS) { b0 = bias[col]; b1 = bias[col + 1]; }
            float v0 = acc[i][j][0] * alpha + b0;
            float v1 = acc[i][j][1] * alpha + b1;
            float v2 = acc[i][j][2] * alpha + b0;
            float v3 = acc[i][j][3] * alpha + b1;
            if (MODE == 0) {
                *(float2*)(Cf + (size_t)row * ldc + col)       = make_float2(v0, v1);
                *(float2*)(Cf + (size_t)(row + 8) * ldc + col) = make_float2(v2, v3);
            } else {
                *(__half2*)(Ch + (size_t)row * ldc + col) =
                    __halves2half2(__float2half_rn(v0), __float2half_rn(v1));
                *(__half2*)(Ch + (size_t)(row + 8) * ldc + col) =
                    __halves2half2(__float2half_rn(v2), __float2half_rn(v3));
            }
        }
    }
}

// ---------------- GEMM wrappers ----------------
__global__ void __launch_bounds__(256, 2) k_qkv(const float* __restrict__ bq,
                                                const float* __restrict__ bk,
                                                const float* __restrict__ bv)
{
    const size_t m0 = (size_t)blockIdx.y * 128, n0 = (size_t)blockIdx.x * 128;
    const size_t co = m0 * U + n0;
    const int z = blockIdx.z;
    if (z == 0) {
        gemm_core<32, 2, true>(g_xh + m0 * U, U, g_Wqh + n0 * U, U,
                               INV_WSCALE, bq + n0, nullptr, g_Qh + co, U);
    } else if (z == 1) {
        gemm_core<32, 2, true>(g_xh + m0 * U, U, g_Wkh + n0 * U, U,
                               INV_WSCALE, bk + n0, nullptr, g_Kh + co, U);
    } else {
        gemm_core<32, 2, true>(g_xh + m0 * U, U, g_Wvh + n0 * U, U,
                               INV_WSCALE, bv + n0, nullptr, g_Vh + co, U);
    }
}

__global__ void __launch_bounds__(256, 2) k_out(const float* __restrict__ bo, float* out)
{
    const size_t m0 = (size_t)blockIdx.y * 128, n0 = (size_t)blockIdx.x * 128;
    gemm_core<32, 0, true>(g_aoh + m0 * U, U, g_Woh + n0 * U, U,
                           INV_WSCALE, bo + n0, out + m0 * U + n0, nullptr, U);
}

__global__ void __launch_bounds__(256, 2) k_scores()
{
    const int z = blockIdx.z, b = z >> 3, h = z & 7;
    const size_t m0 = (size_t)blockIdx.y * 128, n0 = (size_t)blockIdx.x * 128;
    const size_t off = ((size_t)(b * NCHAN + (h >> 2)) * TLEN) * U + (size_t)(h & 3) * 256;
    __half* C = g_sco + (size_t)z * TLEN * TLEN + m0 * TLEN + n0;
    gemm_core<8, 2, false>(g_Qh + off + m0 * U, U, g_Kh + off + n0 * U, U,
                           0.0625f, nullptr, nullptr, C, TLEN);
}

__global__ void __launch_bounds__(256, 2) k_attv()
{
    const int z = blockIdx.z;
    const int b = z >> 4, h = (z >> 1) & 7, n = z & 1;
    const size_t m0 = (size_t)blockIdx.y * 128;
    const size_t aoff = (size_t)(b * HEADS + h) * TLEN * TLEN + m0 * TLEN;
    const size_t boff = (size_t)(b * NCHAN + n) * TLEN * U + (size_t)h * DK * TLEN;
    const size_t coff = ((size_t)(b * NCHAN + n) * TLEN + m0) * U + (size_t)h * DK;
    gemm_core<32, 2, false>(g_atth + aoff, TLEN, g_Vth + boff, TLEN,
                            1.0f, nullptr, nullptr, g_aoh + coff, U);
}

// ---------------- Conversion / softmax kernels ----------------
// x -> fp16; weights -> fp16 of W*WSCALE. One launch.
#define X_F4   2097152u
#define W_F4   262144u
__global__ void __launch_bounds__(256) split_all(
    const float* __restrict__ x,
    const float* __restrict__ Wq, const float* __restrict__ Wk,
    const float* __restrict__ Wv, const float* __restrict__ Wo)
{
    const uint32_t i = blockIdx.x * 256 + threadIdx.x;
    if (i < X_F4) {
        float4 v = ((const float4*)x)[i];
        ((__half2*)(g_xh + (size_t)i * 4))[0] =
            __halves2half2(__float2half_rn(v.x), __float2half_rn(v.y));
        ((__half2*)(g_xh + (size_t)i * 4))[1] =
            __halves2half2(__float2half_rn(v.z), __float2half_rn(v.w));
    } else {
        const uint32_t r = (i - X_F4) >> 18;
        const uint32_t off = (i - X_F4) & (W_F4 - 1);
        const float* src;
        __half* h;
        switch (r) {
            case 0:  src = Wq; h = g_Wqh; break;
            case 1:  src = Wk; h = g_Wkh; break;
            case 2:  src = Wv; h = g_Wvh; break;
            default: src = Wo; h = g_Woh; break;
        }
        float4 v = ((const float4*)src)[off];
        ((__half2*)(h + (size_t)off * 4))[0] =
            __halves2half2(__float2half_rn(v.x * WSCALE), __float2half_rn(v.y * WSCALE));
        ((__half2*)(h + (size_t)off * 4))[1] =
            __halves2half2(__float2half_rn(v.z * WSCALE), __float2half_rn(v.w * WSCALE));
    }
}

// Transpose V per (b,n): Vt[d][s] = V[s][d]  (fp16 -> fp16)
__global__ void vtrans_kernel()
{
    __shared__ __half tile[32][33];
    const int z = blockIdx.z;
    const int d0 = blockIdx.x * 32, s0 = blockIdx.y * 32;
    const __half* src = g_Vh + (size_t)z * TLEN * U;
    tile[threadIdx.y][threadIdx.x] = src[(size_t)(s0 + threadIdx.y) * U + d0 + threadIdx.x];
    __syncthreads();
    const size_t o = (size_t)z * TLEN * U + (size_t)(d0 + threadIdx.y) * TLEN + s0 + threadIdx.x;
    g_Vth[o] = tile[threadIdx.x][threadIdx.y];
}

// Row softmax over fp16 scores -> fp16 att. fp32 internal math.
__global__ void __launch_bounds__(256) softmax_kernel()
{
    const size_t row = blockIdx.x;
    const __half2* p = (const __half2*)(g_sco + row * TLEN);
    const int tid = threadIdx.x;

    float2 a = __half22float2(p[tid * 2]);
    float2 b = __half22float2(p[tid * 2 + 1]);
    float x0 = a.x, x1 = a.y, x2 = b.x, x3 = b.y;

    float m = fmaxf(fmaxf(x0, x1), fmaxf(x2, x3));
#pragma unroll
    for (int o = 16; o; o >>= 1) m = fmaxf(m, __shfl_xor_sync(0xffffffffu, m, o));
    __shared__ float rmax[8], rsum[8];
    if ((tid & 31) == 0) rmax[tid >> 5] = m;
    __syncthreads();
    float bm = fmaxf(fmaxf(fmaxf(rmax[0], rmax[1]), fmaxf(rmax[2], rmax[3])),
                     fmaxf(fmaxf(rmax[4], rmax[5]), fmaxf(rmax[6], rmax[7])));
    float e0 = __expf(x0 - bm), e1 = __expf(x1 - bm);
    float e2 = __expf(x2 - bm), e3 = __expf(x3 - bm);
    float s = e0 + e1 + e2 + e3;
#pragma unroll
    for (int o = 16; o; o >>= 1) s += __shfl_xor_sync(0xffffffffu, s, o);
    if ((tid & 31) == 0) rsum[tid >> 5] = s;
    __syncthreads();
    float inv = 1.0f / (rsum[0] + rsum[1] + rsum[2] + rsum[3]
                      + rsum[4] + rsum[5] + rsum[6] + rsum[7]);

    const size_t base = row * TLEN + (size_t)tid * 4;
    ((__half2*)(g_atth + base))[0] =
        __halves2half2(__float2half_rn(e0 * inv), __float2half_rn(e1 * inv));
    ((__half2*)(g_atth + base))[1] =
        __halves2half2(__float2half_rn(e2 * inv), __float2half_rn(e3 * inv));
}

// ---------------- Launch ----------------
extern "C" void kernel_launch(void* const* d_in, const int* in_sizes, int n_in,
                              void* d_out, int out_size)
{
    const float* x  = (const float*)d_in[0];
    const float* Wq = (const float*)d_in[2];
    const float* bq = (const float*)d_in[3];
    const float* Wk = (const float*)d_in[4];
    const float* bk = (const float*)d_in[5];
    const float* Wv = (const float*)d_in[6];
    const float* bv = (const float*)d_in[7];
    const float* Wo = (const float*)d_in[8];
    const float* bo = (const float*)d_in[9];
    float* out = (float*)d_out;

    cudaFuncSetAttribute(k_qkv,    cudaFuncAttributeMaxDynamicSharedMemorySize, SMEM_BYTES);
    cudaFuncSetAttribute(k_out,    cudaFuncAttributeMaxDynamicSharedMemorySize, SMEM_BYTES);
    cudaFuncSetAttribute(k_scores, cudaFuncAttributeMaxDynamicSharedMemorySize, SMEM_BYTES);
    cudaFuncSetAttribute(k_attv,   cudaFuncAttributeMaxDynamicSharedMemorySize, SMEM_BYTES);

    split_all<<<(X_F4 + 4 * W_F4) / 256, 256>>>(x, Wq, Wk, Wv, Wo);

    k_qkv<<<dim3(8, 64, 3), 256, SMEM_BYTES>>>(bq, bk, bv);

    vtrans_kernel<<<dim3(32, 32, BATCH * NCHAN), dim3(32, 32)>>>();

    k_scores<<<dim3(8, 8, BATCH * HEADS), 256, SMEM_BYTES>>>();

    softmax_kernel<<<BATCH * HEADS * TLEN, 256>>>();

    k_attv<<<dim3(1, 8, BATCH * HEADS * NCHAN), 256, SMEM_BYTES>>>();

    k_out<<<dim3(8, 64), 256, SMEM_BYTES>>>(bo, out);
}

// round 17
// speedup vs baseline: 1.0630x; 1.0630x over previous
#include <cuda_runtime.h>
#include <cuda_fp16.h>
#include <cstdint>

// ---------------- Problem constants ----------------
#define U      1024
#define BATCH  4
#define NCHAN  2
#define TLEN   1024
#define HEADS  8
#define DK     128
#define MROWS  (BATCH * NCHAN * TLEN)          // 8192
#define MS     ((size_t)MROWS * U)             // 8M elements
#define ATTN_E ((size_t)BATCH * HEADS * TLEN * TLEN)  // 32M elements

// Weight pre-scale (exact power of two) keeps fp16 weights in normal range;
// epilogues compensate with alpha = 1/WSCALE.
#define WSCALE     32.0f
#define INV_WSCALE 0.03125f

// ---------------- Scratch (device globals; allocation-free) ----------------
__device__ __half g_xh[MS];                      // x: fp16
__device__ __half g_Wqh[U*U], g_Wkh[U*U], g_Wvh[U*U], g_Woh[U*U];
__device__ __half g_Qh[MS];                      // scores A
__device__ __half g_Kh[MS];                      // scores B
__device__ __half g_Vh[MS];                      // V untransposed, fp16
__device__ __half g_Vth[MS];                     // V transposed, fp16
__device__ __half g_sco[ATTN_E];                 // raw scores, fp16
__device__ __half g_atth[ATTN_E];                // softmaxed att, fp16 (attv A)
__device__ __half g_aoh[MS];                     // attention out (out-proj A)

// ---------------- Helpers ----------------
__device__ __forceinline__ uint32_t smem_u32(const void* p) {
    uint32_t a;
    asm("{ .reg .u64 t; cvta.to.shared.u64 t, %1; cvt.u32.u64 %0, t; }" : "=r"(a) : "l"(p));
    return a;
}
__device__ __forceinline__ void cp16(uint32_t dst, const void* src) {
    asm volatile("cp.async.cg.shared.global [%0], [%1], 16;" :: "r"(dst), "l"(src));
}
#define CP_COMMIT asm volatile("cp.async.commit_group;" ::: "memory")
#define CP_WAIT(n) asm volatile("cp.async.wait_group %0;" :: "n"(n) : "memory")

__device__ __forceinline__ void ldsm4(uint32_t (&r)[4], uint32_t addr) {
    asm volatile("ldmatrix.sync.aligned.m8n8.x4.shared.b16 {%0,%1,%2,%3}, [%4];"
        : "=r"(r[0]), "=r"(r[1]), "=r"(r[2]), "=r"(r[3]) : "r"(addr));
}
__device__ __forceinline__ void mma16816(float (&c)[4], const uint32_t (&a)[4],
                                         uint32_t b0, uint32_t b1) {
    asm volatile(
        "mma.sync.aligned.m16n8k16.row.col.f32.f16.f16.f32 "
        "{%0,%1,%2,%3}, {%4,%5,%6,%7}, {%8,%9}, {%0,%1,%2,%3};"
        : "+f"(c[0]), "+f"(c[1]), "+f"(c[2]), "+f"(c[3])
        : "r"(a[0]), "r"(a[1]), "r"(a[2]), "r"(a[3]), "r"(b0), "r"(b1));
}

// ---------------- fp16 GEMM core (mma.sync) ----------------
// C[128,128] = alpha*(A@B^T) + bias.  A, B fp16, K-major.
// 256 threads. BK=64: tile 128 rows x 64 fp16 (128B data), row stride 144B
// (r*36 mod 32 = {0,4,..,28}: ldmatrix conflict-free). 3-stage cp.async ring.
#define TROW     144
#define TILE_B   (128 * TROW)              // 18432
#define SM_AH    0
#define SM_BH    TILE_B
#define SMEM_STAGE (2 * TILE_B)            // 36864
#define SMEM_BYTES (3 * SMEM_STAGE)        // 110592 (2 CTAs/SM: <=114688)

__device__ __forceinline__ void stage_tile(uint32_t sdst, const __half* __restrict__ g,
                                           int ld, int tid) {
#pragma unroll
    for (int p = 0; p < 4; ++p) {
        int idx = p * 256 + tid;           // 1024 chunks of 16B (128 rows x 8)
        int row = idx >> 3, c = idx & 7;
        cp16(sdst + row * TROW + c * 16, g + (size_t)row * ld + c * 8);
    }
}

// MODE 0: fp32 out (Cf). MODE 2: fp16 out (Ch).
template <int NST, int MODE, bool HAS_BIAS>
__device__ __forceinline__ void gemm_core(
    const __half* __restrict__ Ah, int lda,
    const __half* __restrict__ Bh, int ldb,
    float alpha, const float* __restrict__ bias,
    float* Cf, __half* Ch, int ldc)
{
    extern __shared__ char smem[];
    const uint32_t sb = smem_u32(smem);
    const int tid = threadIdx.x;
    const int l   = tid & 31;
    const int wid = tid >> 5;
    const int wm  = wid >> 1;      // 0..3 -> M
    const int wn  = wid & 1;       // 0..1 -> N

    const uint32_t lrow = (uint32_t)(l & 15) * TROW + (uint32_t)(l >> 4) * 16;
    const uint32_t aoff = (uint32_t)(wm * 32) * TROW + lrow;
    const uint32_t boff = (uint32_t)(wn * 64) * TROW + lrow;

    float acc[2][8][4];
#pragma unroll
    for (int i = 0; i < 2; ++i)
#pragma unroll
        for (int j = 0; j < 8; ++j)
#pragma unroll
            for (int q = 0; q < 4; ++q) acc[i][j][q] = 0.0f;

    // prologue: stages 0 and 1 in flight
    stage_tile(sb + SM_AH, Ah, lda, tid);
    stage_tile(sb + SM_BH, Bh, ldb, tid);
    CP_COMMIT;
    if (NST > 1) {
        stage_tile(sb + SMEM_STAGE + SM_AH, Ah + 64, lda, tid);
        stage_tile(sb + SMEM_STAGE + SM_BH, Bh + 64, ldb, tid);
        CP_COMMIT;
    }

    for (int st = 0; st < NST; ++st) {
        if (st + 1 < NST) { CP_WAIT(1); }  // stage st landed; st+1 may fly
        else              { CP_WAIT(0); }
        __syncthreads();   // one barrier/stage; buffer (st+2)%3's old readers
                           // (stage st-1) are behind this barrier

        if (st + 2 < NST) {
            const uint32_t so2 = (uint32_t)((st + 2) % 3) * SMEM_STAGE;
            const int k0 = (st + 2) << 6;
            stage_tile(sb + so2 + SM_AH, Ah + k0, lda, tid);
            stage_tile(sb + so2 + SM_BH, Bh + k0, ldb, tid);
            CP_COMMIT;
        }

        const uint32_t so = (uint32_t)(st % 3) * SMEM_STAGE;
#pragma unroll
        for (int k16 = 0; k16 < 4; ++k16) {
            const uint32_t kb = (uint32_t)k16 * 32;
            uint32_t ah[2][4];
#pragma unroll
            for (int i = 0; i < 2; ++i)
                ldsm4(ah[i], sb + so + SM_AH + aoff + i * (16 * TROW) + kb);
#pragma unroll
            for (int j2 = 0; j2 < 4; ++j2) {
                uint32_t bh[4];
                ldsm4(bh, sb + so + SM_BH + boff + j2 * (16 * TROW) + kb);
#pragma unroll
                for (int jj = 0; jj < 2; ++jj) {
#pragma unroll
                    for (int i = 0; i < 2; ++i) {
                        const int j = j2 * 2 + jj;
                        mma16816(acc[i][j], ah[i], bh[jj], bh[jj + 2]);
                    }
                }
            }
        }
    }

    // ---- Epilogue ----
    const int rbase = wm * 32 + (l >> 2);
    const int cbase = wn * 64 + 2 * (l & 3);
#pragma unroll
    for (int i = 0; i < 2; ++i) {
#pragma unroll
        for (int j = 0; j < 8; ++j) {
            const int row = rbase + i * 16;
            const int col = cbase + j * 8;
            float b0 = 0.0f, b1 = 0.0f;
            if (HAS_BIAS) { b0 = bias[col]; b1 = bias[col + 1]; }
            float v0 = acc[i][j][0] * alpha + b0;
            float v1 = acc[i][j][1] * alpha + b1;
            float v2 = acc[i][j][2] * alpha + b0;
            float v3 = acc[i][j][3] * alpha + b1;
            if (MODE == 0) {
                *(float2*)(Cf + (size_t)row * ldc + col)       = make_float2(v0, v1);
                *(float2*)(Cf + (size_t)(row + 8) * ldc + col) = make_float2(v2, v3);
            } else {
                *(__half2*)(Ch + (size_t)row * ldc + col) =
                    __halves2half2(__float2half_rn(v0), __float2half_rn(v1));
                *(__half2*)(Ch + (size_t)(row + 8) * ldc + col) =
                    __halves2half2(__float2half_rn(v2), __float2half_rn(v3));
            }
        }
    }
}

// ---------------- GEMM wrappers ----------------
__global__ void __launch_bounds__(256, 2) k_qkv(const float* __restrict__ bq,
                                                const float* __restrict__ bk,
                                                const float* __restrict__ bv)
{
    const size_t m0 = (size_t)blockIdx.y * 128, n0 = (size_t)blockIdx.x * 128;
    const size_t co = m0 * U + n0;
    const int z = blockIdx.z;
    if (z == 0) {
        gemm_core<16, 2, true>(g_xh + m0 * U, U, g_Wqh + n0 * U, U,
                               INV_WSCALE, bq + n0, nullptr, g_Qh + co, U);
    } else if (z == 1) {
        gemm_core<16, 2, true>(g_xh + m0 * U, U, g_Wkh + n0 * U, U,
                               INV_WSCALE, bk + n0, nullptr, g_Kh + co, U);
    } else {
        gemm_core<16, 2, true>(g_xh + m0 * U, U, g_Wvh + n0 * U, U,
                               INV_WSCALE, bv + n0, nullptr, g_Vh + co, U);
    }
}

__global__ void __launch_bounds__(256, 2) k_out(const float* __restrict__ bo, float* out)
{
    const size_t m0 = (size_t)blockIdx.y * 128, n0 = (size_t)blockIdx.x * 128;
    gemm_core<16, 0, true>(g_aoh + m0 * U, U, g_Woh + n0 * U, U,
                           INV_WSCALE, bo + n0, out + m0 * U + n0, nullptr, U);
}

__global__ void __launch_bounds__(256, 2) k_scores()
{
    const int z = blockIdx.z, b = z >> 3, h = z & 7;
    const size_t m0 = (size_t)blockIdx.y * 128, n0 = (size_t)blockIdx.x * 128;
    const size_t off = ((size_t)(b * NCHAN + (h >> 2)) * TLEN) * U + (size_t)(h & 3) * 256;
    __half* C = g_sco + (size_t)z * TLEN * TLEN + m0 * TLEN + n0;
    gemm_core<4, 2, false>(g_Qh + off + m0 * U, U, g_Kh + off + n0 * U, U,
                           0.0625f, nullptr, nullptr, C, TLEN);
}

__global__ void __launch_bounds__(256, 2) k_attv()
{
    const int z = blockIdx.z;
    const int b = z >> 4, h = (z >> 1) & 7, n = z & 1;
    const size_t m0 = (size_t)blockIdx.y * 128;
    const size_t aoff = (size_t)(b * HEADS + h) * TLEN * TLEN + m0 * TLEN;
    const size_t boff = (size_t)(b * NCHAN + n) * TLEN * U + (size_t)h * DK * TLEN;
    const size_t coff = ((size_t)(b * NCHAN + n) * TLEN + m0) * U + (size_t)h * DK;
    gemm_core<16, 2, false>(g_atth + aoff, TLEN, g_Vth + boff, TLEN,
                            1.0f, nullptr, nullptr, g_aoh + coff, U);
}

// ---------------- Conversion / softmax kernels ----------------
// x -> fp16; weights -> fp16 of W*WSCALE. One launch.
#define X_F4   2097152u
#define W_F4   262144u
__global__ void __launch_bounds__(256) split_all(
    const float* __restrict__ x,
    const float* __restrict__ Wq, const float* __restrict__ Wk,
    const float* __restrict__ Wv, const float* __restrict__ Wo)
{
    const uint32_t i = blockIdx.x * 256 + threadIdx.x;
    if (i < X_F4) {
        float4 v = ((const float4*)x)[i];
        ((__half2*)(g_xh + (size_t)i * 4))[0] =
            __halves2half2(__float2half_rn(v.x), __float2half_rn(v.y));
        ((__half2*)(g_xh + (size_t)i * 4))[1] =
            __halves2half2(__float2half_rn(v.z), __float2half_rn(v.w));
    } else {
        const uint32_t r = (i - X_F4) >> 18;
        const uint32_t off = (i - X_F4) & (W_F4 - 1);
        const float* src;
        __half* h;
        switch (r) {
            case 0:  src = Wq; h = g_Wqh; break;
            case 1:  src = Wk; h = g_Wkh; break;
            case 2:  src = Wv; h = g_Wvh; break;
            default: src = Wo; h = g_Woh; break;
        }
        float4 v = ((const float4*)src)[off];
        ((__half2*)(h + (size_t)off * 4))[0] =
            __halves2half2(__float2half_rn(v.x * WSCALE), __float2half_rn(v.y * WSCALE));
        ((__half2*)(h + (size_t)off * 4))[1] =
            __halves2half2(__float2half_rn(v.z * WSCALE), __float2half_rn(v.w * WSCALE));
    }
}

// Transpose V per (b,n): Vt[d][s] = V[s][d]  (fp16 -> fp16)
__global__ void vtrans_kernel()
{
    __shared__ __half tile[32][33];
    const int z = blockIdx.z;
    const int d0 = blockIdx.x * 32, s0 = blockIdx.y * 32;
    const __half* src = g_Vh + (size_t)z * TLEN * U;
    tile[threadIdx.y][threadIdx.x] = src[(size_t)(s0 + threadIdx.y) * U + d0 + threadIdx.x];
    __syncthreads();
    const size_t o = (size_t)z * TLEN * U + (size_t)(d0 + threadIdx.y) * TLEN + s0 + threadIdx.x;
    g_Vth[o] = tile[threadIdx.x][threadIdx.y];
}

// Row softmax over fp16 scores -> fp16 att. fp32 internal math.
__global__ void __launch_bounds__(256) softmax_kernel()
{
    const size_t row = blockIdx.x;
    const __half2* p = (const __half2*)(g_sco + row * TLEN);
    const int tid = threadIdx.x;

    float2 a = __half22float2(p[tid * 2]);
    float2 b = __half22float2(p[tid * 2 + 1]);
    float x0 = a.x, x1 = a.y, x2 = b.x, x3 = b.y;

    float m = fmaxf(fmaxf(x0, x1), fmaxf(x2, x3));
#pragma unroll
    for (int o = 16; o; o >>= 1) m = fmaxf(m, __shfl_xor_sync(0xffffffffu, m, o));
    __shared__ float rmax[8], rsum[8];
    if ((tid & 31) == 0) rmax[tid >> 5] = m;
    __syncthreads();
    float bm = fmaxf(fmaxf(fmaxf(rmax[0], rmax[1]), fmaxf(rmax[2], rmax[3])),
                     fmaxf(fmaxf(rmax[4], rmax[5]), fmaxf(rmax[6], rmax[7])));
    float e0 = __expf(x0 - bm), e1 = __expf(x1 - bm);
    float e2 = __expf(x2 - bm), e3 = __expf(x3 - bm);
    float s = e0 + e1 + e2 + e3;
#pragma unroll
    for (int o = 16; o; o >>= 1) s += __shfl_xor_sync(0xffffffffu, s, o);
    if ((tid & 31) == 0) rsum[tid >> 5] = s;
    __syncthreads();
    float inv = 1.0f / (rsum[0] + rsum[1] + rsum[2] + rsum[3]
                      + rsum[4] + rsum[5] + rsum[6] + rsum[7]);

    const size_t base = row * TLEN + (size_t)tid * 4;
    ((__half2*)(g_atth + base))[0] =
        __halves2half2(__float2half_rn(e0 * inv), __float2half_rn(e1 * inv));
    ((__half2*)(g_atth + base))[1] =
        __halves2half2(__float2half_rn(e2 * inv), __float2half_rn(e3 * inv));
}

// ---------------- Launch ----------------
extern "C" void kernel_launch(void* const* d_in, const int* in_sizes, int n_in,
                              void* d_out, int out_size)
{
    const float* x  = (const float*)d_in[0];
    const float* Wq = (const float*)d_in[2];
    const float* bq = (const float*)d_in[3];
    const float* Wk = (const float*)d_in[4];
    const float* bk = (const float*)d_in[5];
    const float* Wv = (const float*)d_in[6];
    const float* bv = (const float*)d_in[7];
    const float* Wo = (const float*)d_in[8];
    const float* bo = (const float*)d_in[9];
    float* out = (float*)d_out;

    cudaFuncSetAttribute(k_qkv,    cudaFuncAttributeMaxDynamicSharedMemorySize, SMEM_BYTES);
    cudaFuncSetAttribute(k_out,    cudaFuncAttributeMaxDynamicSharedMemorySize, SMEM_BYTES);
    cudaFuncSetAttribute(k_scores, cudaFuncAttributeMaxDynamicSharedMemorySize, SMEM_BYTES);
    cudaFuncSetAttribute(k_attv,   cudaFuncAttributeMaxDynamicSharedMemorySize, SMEM_BYTES);

    split_all<<<(X_F4 + 4 * W_F4) / 256, 256>>>(x, Wq, Wk, Wv, Wo);

    k_qkv<<<dim3(8, 64, 3), 256, SMEM_BYTES>>>(bq, bk, bv);

    vtrans_kernel<<<dim3(32, 32, BATCH * NCHAN), dim3(32, 32)>>>();

    k_scores<<<dim3(8, 8, BATCH * HEADS), 256, SMEM_BYTES>>>();

    softmax_kernel<<<BATCH * HEADS * TLEN, 256>>>();

    k_attv<<<dim3(1, 8, BATCH * HEADS * NCHAN), 256, SMEM_BYTES>>>();

    k_out<<<dim3(8, 64), 256, SMEM_BYTES>>>(bo, out);
}